// round 9
// baseline (speedup 1.0000x reference)
#include <cuda_runtime.h>
#include <cuda_bf16.h>

#define NODES_MAX 50000
#define FEATS 128
#define KNBR 20

// bf16 copy of V (for cheap gathers) and G hi/lo planes, row-major [N][128]
__device__ __nv_bfloat16 g_Vb[NODES_MAX * FEATS];
__device__ __nv_bfloat16 g_Gh[NODES_MAX * FEATS];
__device__ __nv_bfloat16 g_Gl[NODES_MAX * FEATS];

// =================== helpers ===================
__device__ __forceinline__ unsigned int smem_u32(const void* p) {
    unsigned int a;
    asm("{ .reg .u64 t; cvta.to.shared.u64 t, %1; cvt.u32.u64 %0, t; }"
        : "=r"(a) : "l"(p));
    return a;
}
__device__ __forceinline__ void ldsm4(unsigned int r[4], unsigned int addr) {
    asm volatile("ldmatrix.sync.aligned.m8n8.x4.shared.b16 {%0,%1,%2,%3}, [%4];"
                 : "=r"(r[0]), "=r"(r[1]), "=r"(r[2]), "=r"(r[3])
                 : "r"(addr));
}
__device__ __forceinline__ void mma16816(float c[4], const unsigned int a[4],
                                         unsigned int b0, unsigned int b1) {
    asm volatile(
        "mma.sync.aligned.m16n8k16.row.col.f32.bf16.bf16.f32 "
        "{%0,%1,%2,%3}, {%4,%5,%6,%7}, {%8,%9}, {%0,%1,%2,%3};"
        : "+f"(c[0]), "+f"(c[1]), "+f"(c[2]), "+f"(c[3])
        : "r"(a[0]), "r"(a[1]), "r"(a[2]), "r"(a[3]), "r"(b0), "r"(b1));
}
__device__ __forceinline__ void cp16(unsigned int dst, const void* src) {
    asm volatile("cp.async.cg.shared.global [%0], [%1], 16;"
                 :: "r"(dst), "l"(__cvta_generic_to_global(src)) : "memory");
}
#define CP_COMMIT() asm volatile("cp.async.commit_group;" ::: "memory")
#define CP_WAIT0()  asm volatile("cp.async.wait_group 0;" ::: "memory")

__device__ __forceinline__ unsigned int sw128(unsigned int b) {
    return b ^ ((b >> 3) & 0x70);
}
// [128 x 128] bf16 K-major tile = two 64-k planes of 16KB, 128B rows
__device__ __forceinline__ unsigned int tile_off(int row, int k) {
    return ((unsigned)(k >> 6) << 14) + ((unsigned)row << 7) + ((unsigned)(k & 63) << 1);
}
__device__ __forceinline__ unsigned int pack2bf(float a, float b) {
    __nv_bfloat162 p = __floats2bfloat162_rn(a, b);
    return *reinterpret_cast<unsigned int*>(&p);
}
// split a float2 into bf16x2 hi and lo fragment regs
__device__ __forceinline__ void splitfrag(float2 v, unsigned int& hi, unsigned int& lo) {
    __nv_bfloat162 h = __floats2bfloat162_rn(v.x, v.y);
    float hx = __bfloat162float(h.x);
    float hy = __bfloat162float(h.y);
    __nv_bfloat162 l = __floats2bfloat162_rn(v.x - hx, v.y - hy);
    hi = *reinterpret_cast<unsigned int*>(&h);
    lo = *reinterpret_cast<unsigned int*>(&l);
}

// shared weight-conversion routine: W[k][n] fp32 -> hi/lo bf16 [n][k] SW128 planes
__device__ __forceinline__ void convert_weights(const float* __restrict__ W,
                                                char* bh, char* bl, int tid, int nthr) {
    for (int idx = tid; idx < 4096; idx += nthr) {
        int k  = idx >> 5;
        int n4 = (idx & 31) << 2;
        float4 w = *reinterpret_cast<const float4*>(W + k * FEATS + n4);
        float wv[4] = {w.x, w.y, w.z, w.w};
#pragma unroll
        for (int i = 0; i < 4; i++) {
            __nv_bfloat16 h = __float2bfloat16(wv[i]);
            float hf = __bfloat162float(h);
            __nv_bfloat16 l = __float2bfloat16(wv[i] - hf);
            unsigned int off = sw128(tile_off(n4 + i, k));
            *reinterpret_cast<__nv_bfloat16*>(bh + off) = h;
            *reinterpret_cast<__nv_bfloat16*>(bl + off) = l;
        }
    }
}

// ---------------- Kernel 0: V -> bf16 copy ----------------
__global__ void conv_kernel(const float4* __restrict__ X4, int n4) {
    int i = blockIdx.x * blockDim.x + threadIdx.x;
    if (i < n4) {
        float4 v = X4[i];
        uint2 u;
        u.x = pack2bf(v.x, v.y);
        u.y = pack2bf(v.z, v.w);
        reinterpret_cast<uint2*>(g_Vb)[i] = u;
    }
}

// ---------------- Kernel 1: gather-aggregate (bf16 rows) ----------------
__global__ void agg_kernel(const int* __restrict__ nh_idx,
                           const int* __restrict__ int_idx,
                           const float* __restrict__ nh_e,
                           const float* __restrict__ int_e,
                           int n) {
    int node = blockIdx.x * (blockDim.x >> 5) + (threadIdx.x >> 5);
    if (node >= n) return;
    int lane = threadIdx.x & 31;
    const uint2* Vb2 = reinterpret_cast<const uint2*>(g_Vb);

    int   iA = -1, iB = -1;
    float eA = 0.f, eB = 0.f;
    if (lane < KNBR) {
        int base = node * KNBR + lane;
        iA = nh_idx[base];
        eA = nh_e[base];
        iB = int_idx[base];
        eB = int_e[base];
    }
    int validB = __popc(__ballot_sync(0xffffffffu, (lane < KNBR) && (iB >= 0)));

    float4 acc = make_float4(0.f, 0.f, 0.f, 0.f);
#pragma unroll
    for (int j = 0; j < KNBR; j++) {
        int   idx = __shfl_sync(0xffffffffu, iA, j);
        float e   = __shfl_sync(0xffffffffu, eA, j);
        uint2 u   = __ldg(&Vb2[idx * 32 + lane]);
        __nv_bfloat162 p0 = *reinterpret_cast<__nv_bfloat162*>(&u.x);
        __nv_bfloat162 p1 = *reinterpret_cast<__nv_bfloat162*>(&u.y);
        acc.x = fmaf(e, __bfloat162float(p0.x), acc.x);
        acc.y = fmaf(e, __bfloat162float(p0.y), acc.y);
        acc.z = fmaf(e, __bfloat162float(p1.x), acc.z);
        acc.w = fmaf(e, __bfloat162float(p1.y), acc.w);
    }
#pragma unroll
    for (int j = 0; j < KNBR; j++) {
        int idx = __shfl_sync(0xffffffffu, iB, j);
        if (idx >= 0) {
            float e  = __shfl_sync(0xffffffffu, eB, j);
            uint2 u  = __ldg(&Vb2[idx * 32 + lane]);
            __nv_bfloat162 p0 = *reinterpret_cast<__nv_bfloat162*>(&u.x);
            __nv_bfloat162 p1 = *reinterpret_cast<__nv_bfloat162*>(&u.y);
            acc.x = fmaf(e, __bfloat162float(p0.x), acc.x);
            acc.y = fmaf(e, __bfloat162float(p0.y), acc.y);
            acc.z = fmaf(e, __bfloat162float(p1.x), acc.z);
            acc.w = fmaf(e, __bfloat162float(p1.y), acc.w);
        }
    }
    float inv = 1.0f / (float)(KNBR + validB);
    float gv[4] = {acc.x * inv, acc.y * inv, acc.z * inv, acc.w * inv};
    float hf[4];
#pragma unroll
    for (int q = 0; q < 4; q++)
        hf[q] = __bfloat162float(__float2bfloat16(gv[q]));
    uint2 hi = make_uint2(pack2bf(hf[0], hf[1]), pack2bf(hf[2], hf[3]));
    uint2 lo = make_uint2(pack2bf(gv[0] - hf[0], gv[1] - hf[1]),
                          pack2bf(gv[2] - hf[2], gv[3] - hf[3]));
    reinterpret_cast<uint2*>(g_Gh)[node * 32 + lane] = hi;
    reinterpret_cast<uint2*>(g_Gl)[node * 32 + lane] = lo;
}

// ---------------- Kernel 2: V-GEMM (out = V @ Wvc, fp32 raw) ----------------
#define SMV_TOTAL 65536
__global__ __launch_bounds__(256, 1)
void gemmV(const float* __restrict__ X,
           const float* __restrict__ Wvc,
           float* __restrict__ out, int n) {
    extern __shared__ char smem[];
    unsigned int sb = smem_u32(smem);
    const int tid = threadIdx.x;
    const int wid = tid >> 5;
    const int lane = tid & 31;

    convert_weights(Wvc, smem, smem + 32768, tid, 256);
    __syncthreads();

    const int wm = wid & 1;
    const int wn = wid >> 1;
    const int mIdx = lane >> 3;
    const int r8 = lane & 7;
    const int rowB = wn * 32 + ((mIdx >> 1) << 3) + r8;
    const unsigned int prowB =
        ((unsigned)rowB << 7) ^ ((unsigned)r8 << 4) ^ (((unsigned)mIdx & 1) << 4);

    const int tile = blockIdx.x;
    float acc[4][4][4];
#pragma unroll
    for (int rb = 0; rb < 4; rb++)
#pragma unroll
        for (int cb = 0; cb < 4; cb++)
#pragma unroll
            for (int q = 0; q < 4; q++) acc[rb][cb][q] = 0.f;

    const unsigned int WH = sb;
    const unsigned int WL = sb + 32768u;
    const int rbase = tile * 128 + wm * 64 + (lane >> 2);
#pragma unroll
    for (int ks = 0; ks < 8; ks++) {
        const unsigned int Kc = (((unsigned)ks >> 2) << 14) | (((unsigned)ks & 3) << 5);
        unsigned int bh[2][4], bl[2][4];
        ldsm4(bh[0], WH + (prowB ^ Kc));
        ldsm4(bh[1], WH + (prowB ^ 0x800u ^ Kc));
        ldsm4(bl[0], WL + (prowB ^ Kc));
        ldsm4(bl[1], WL + (prowB ^ 0x800u ^ Kc));

        const int kb = ks * 16 + ((lane & 3) << 1);
        unsigned int ah[4][4], al[4][4];
#pragma unroll
        for (int rb = 0; rb < 4; rb++) {
            int r0 = rbase + rb * 16;
            int r1 = r0 + 8;
            if (r0 >= n) r0 = n - 1;
            if (r1 >= n) r1 = n - 1;
            const float* p0 = X + (long long)r0 * FEATS + kb;
            const float* p1 = X + (long long)r1 * FEATS + kb;
            splitfrag(*reinterpret_cast<const float2*>(p0),     ah[rb][0], al[rb][0]);
            splitfrag(*reinterpret_cast<const float2*>(p1),     ah[rb][1], al[rb][1]);
            splitfrag(*reinterpret_cast<const float2*>(p0 + 8), ah[rb][2], al[rb][2]);
            splitfrag(*reinterpret_cast<const float2*>(p1 + 8), ah[rb][3], al[rb][3]);
        }
#pragma unroll
        for (int rb = 0; rb < 4; rb++) {
#pragma unroll
            for (int cb = 0; cb < 4; cb++) {
                unsigned int b0h = bh[cb >> 1][(cb & 1) * 2];
                unsigned int b1h = bh[cb >> 1][(cb & 1) * 2 + 1];
                unsigned int b0l = bl[cb >> 1][(cb & 1) * 2];
                unsigned int b1l = bl[cb >> 1][(cb & 1) * 2 + 1];
                mma16816(acc[rb][cb], ah[rb], b0h, b1h);
                mma16816(acc[rb][cb], ah[rb], b0l, b1l);
                mma16816(acc[rb][cb], al[rb], b0h, b1h);
            }
        }
    }

    // raw fp32 store (no bias/relu yet)
#pragma unroll
    for (int rb = 0; rb < 4; rb++) {
        int r0 = rbase + rb * 16;
        int r1 = r0 + 8;
#pragma unroll
        for (int cb = 0; cb < 4; cb++) {
            int col = wn * 32 + cb * 8 + ((lane & 3) << 1);
            if (r0 < n)
                *reinterpret_cast<float2*>(out + (long long)r0 * FEATS + col) =
                    make_float2(acc[rb][cb][0], acc[rb][cb][1]);
            if (r1 < n)
                *reinterpret_cast<float2*>(out + (long long)r1 * FEATS + col) =
                    make_float2(acc[rb][cb][2], acc[rb][cb][3]);
        }
    }
}

// ---------------- Kernel 3: G-GEMM (out = relu(out + G @ Wvn + bv)) ----------------
#define SMG_G 65536u
#define SMG_TOTAL 131072
__global__ __launch_bounds__(256, 1)
void gemmG(const float* __restrict__ Wvn,
           const float* __restrict__ bv,
           float* __restrict__ out, int n) {
    extern __shared__ char smem[];
    unsigned int sb = smem_u32(smem);
    const int tid = threadIdx.x;
    const int wid = tid >> 5;
    const int lane = tid & 31;
    const int tile = blockIdx.x;

    // fill G tile (hi at SMG_G, lo at +32KB) via cp.async
#pragma unroll
    for (int i = 0; i < 8; i++) {
        int u = i * 256 + tid;       // 0..2047 16B-units per plane
        int row = u >> 4;
        int w = u & 15;
        int h = w >> 3;
        int uu = w & 7;
        int gr = tile * 128 + row;
        if (gr >= n) gr = n - 1;
        unsigned int off = sw128(((unsigned)h << 14) | ((unsigned)row << 7) | ((unsigned)uu << 4));
        long long sOff = (long long)gr * 256 + h * 128 + uu * 16;
        cp16(sb + SMG_G + off, (const char*)g_Gh + sOff);
        cp16(sb + SMG_G + 32768u + off, (const char*)g_Gl + sOff);
    }
    CP_COMMIT();

    convert_weights(Wvn, smem, smem + 32768, tid, 256);
    CP_WAIT0();
    __syncthreads();

    const int wm = wid & 1;
    const int wn = wid >> 1;
    const int mIdx = lane >> 3;
    const int r8 = lane & 7;
    const int rowGA = wm * 64 + ((mIdx & 1) << 3) + r8;
    const unsigned int prowA =
        ((unsigned)rowGA << 7) ^ ((unsigned)r8 << 4) ^ (((unsigned)mIdx >> 1) << 4);
    const int rowB = wn * 32 + ((mIdx >> 1) << 3) + r8;
    const unsigned int prowB =
        ((unsigned)rowB << 7) ^ ((unsigned)r8 << 4) ^ (((unsigned)mIdx & 1) << 4);

    const unsigned int GH = sb + SMG_G;
    const unsigned int GL = GH + 32768u;
    const unsigned int WH = sb;
    const unsigned int WL = sb + 32768u;

    float acc[4][4][4];
#pragma unroll
    for (int rb = 0; rb < 4; rb++)
#pragma unroll
        for (int cb = 0; cb < 4; cb++)
#pragma unroll
            for (int q = 0; q < 4; q++) acc[rb][cb][q] = 0.f;

#pragma unroll
    for (int ks = 0; ks < 8; ks++) {
        const unsigned int Kc = (((unsigned)ks >> 2) << 14) | (((unsigned)ks & 3) << 5);
        unsigned int bh[2][4], bl[2][4];
        ldsm4(bh[0], WH + (prowB ^ Kc));
        ldsm4(bh[1], WH + (prowB ^ 0x800u ^ Kc));
        ldsm4(bl[0], WL + (prowB ^ Kc));
        ldsm4(bl[1], WL + (prowB ^ 0x800u ^ Kc));

        unsigned int ah[4][4], al[4][4];
#pragma unroll
        for (int rb = 0; rb < 4; rb++) {
            unsigned int ra = (prowA ^ ((unsigned)rb << 11)) ^ Kc;
            ldsm4(ah[rb], GH + ra);
            ldsm4(al[rb], GL + ra);
        }
#pragma unroll
        for (int rb = 0; rb < 4; rb++) {
#pragma unroll
            for (int cb = 0; cb < 4; cb++) {
                unsigned int b0h = bh[cb >> 1][(cb & 1) * 2];
                unsigned int b1h = bh[cb >> 1][(cb & 1) * 2 + 1];
                unsigned int b0l = bl[cb >> 1][(cb & 1) * 2];
                unsigned int b1l = bl[cb >> 1][(cb & 1) * 2 + 1];
                mma16816(acc[rb][cb], ah[rb], b0h, b1h);
                mma16816(acc[rb][cb], ah[rb], b0l, b1l);
                mma16816(acc[rb][cb], al[rb], b0h, b1h);
            }
        }
    }

    float2 biasj[4];
#pragma unroll
    for (int j = 0; j < 4; j++) {
        int c = wn * 32 + j * 8 + ((lane & 3) << 1);
        biasj[j].x = __ldg(bv + c);
        biasj[j].y = __ldg(bv + c + 1);
    }

    const int rbase = tile * 128 + wm * 64 + (lane >> 2);
#pragma unroll
    for (int rb = 0; rb < 4; rb++) {
        int r0 = rbase + rb * 16;
        int r1 = r0 + 8;
#pragma unroll
        for (int cb = 0; cb < 4; cb++) {
            int col = wn * 32 + cb * 8 + ((lane & 3) << 1);
            if (r0 < n) {
                float2* p = reinterpret_cast<float2*>(out + (long long)r0 * FEATS + col);
                float2 zc = *p;
                p->x = fmaxf(zc.x + acc[rb][cb][0] + biasj[cb].x, 0.f);
                p->y = fmaxf(zc.y + acc[rb][cb][1] + biasj[cb].y, 0.f);
            }
            if (r1 < n) {
                float2* p = reinterpret_cast<float2*>(out + (long long)r1 * FEATS + col);
                float2 zc = *p;
                p->x = fmaxf(zc.x + acc[rb][cb][2] + biasj[cb].x, 0.f);
                p->y = fmaxf(zc.y + acc[rb][cb][3] + biasj[cb].y, 0.f);
            }
        }
    }
}

// ---------------- host side: capture-time stream fork ----------------
static cudaStream_t g_s2;
static cudaEvent_t g_e0, g_e1;
static bool g_ok = []() {
    if (cudaStreamCreateWithFlags(&g_s2, cudaStreamNonBlocking) != cudaSuccess) return false;
    if (cudaEventCreateWithFlags(&g_e0, cudaEventDisableTiming) != cudaSuccess) return false;
    if (cudaEventCreateWithFlags(&g_e1, cudaEventDisableTiming) != cudaSuccess) return false;
    return true;
}();

extern "C" void kernel_launch(void* const* d_in, const int* in_sizes, int n_in,
                              void* d_out, int out_size) {
    const float* vertices = (const float*)d_in[0];
    const int*   nh_idx   = (const int*)d_in[1];
    const int*   int_idx  = (const int*)d_in[2];
    const float* nh_e     = (const float*)d_in[3];
    const float* int_e    = (const float*)d_in[4];
    const float* Wvc      = (const float*)d_in[5];
    const float* Wvn      = (const float*)d_in[6];
    const float* bv       = (const float*)d_in[7];
    float* out = (float*)d_out;

    int n = in_sizes[0] / FEATS;  // 50000
    int ntiles = (n + 127) / 128;

    static bool attr_done = false;
    if (!attr_done) {
        cudaFuncSetAttribute(gemmV, cudaFuncAttributeMaxDynamicSharedMemorySize, SMV_TOTAL);
        cudaFuncSetAttribute(gemmG, cudaFuncAttributeMaxDynamicSharedMemorySize, SMG_TOTAL);
        attr_done = true;
    }

    cudaStream_t s2 = g_ok ? g_s2 : (cudaStream_t)0;

    if (g_ok) {
        // fork: convert + aggregate on s2, gemmV on main
        cudaEventRecord(g_e0, 0);
        cudaStreamWaitEvent(s2, g_e0, 0);
    }
    int n4 = n * 32;
    conv_kernel<<<(n4 + 255) / 256, 256, 0, s2>>>((const float4*)vertices, n4);
    agg_kernel<<<(n + 7) / 8, 256, 0, s2>>>(nh_idx, int_idx, nh_e, int_e, n);
    if (g_ok) cudaEventRecord(g_e1, s2);

    gemmV<<<ntiles, 256, SMV_TOTAL>>>(vertices, Wvc, out, n);

    if (g_ok) cudaStreamWaitEvent(0, g_e1, 0);
    gemmG<<<ntiles, 256, SMG_TOTAL>>>(Wvn, bv, out, n);
}

// round 10
// speedup vs baseline: 1.5774x; 1.5774x over previous
#include <cuda_runtime.h>
#include <cuda_bf16.h>

#define NODES_MAX 50000
#define FEATS 128
#define KNBR 20

// Pre-converted bf16 planes: V hi/lo (exact split), G hi/lo (from bf16 gathers)
__device__ __nv_bfloat16 g_Vh[NODES_MAX * FEATS];
__device__ __nv_bfloat16 g_Vl[NODES_MAX * FEATS];
__device__ __nv_bfloat16 g_Gh[NODES_MAX * FEATS];
__device__ __nv_bfloat16 g_Gl[NODES_MAX * FEATS];

// =================== helpers ===================
__device__ __forceinline__ unsigned int smem_u32(const void* p) {
    unsigned int a;
    asm("{ .reg .u64 t; cvta.to.shared.u64 t, %1; cvt.u32.u64 %0, t; }"
        : "=r"(a) : "l"(p));
    return a;
}
__device__ __forceinline__ void ldsm4(unsigned int r[4], unsigned int addr) {
    asm volatile("ldmatrix.sync.aligned.m8n8.x4.shared.b16 {%0,%1,%2,%3}, [%4];"
                 : "=r"(r[0]), "=r"(r[1]), "=r"(r[2]), "=r"(r[3])
                 : "r"(addr));
}
__device__ __forceinline__ void mma16816(float c[4], const unsigned int a[4],
                                         unsigned int b0, unsigned int b1) {
    asm volatile(
        "mma.sync.aligned.m16n8k16.row.col.f32.bf16.bf16.f32 "
        "{%0,%1,%2,%3}, {%4,%5,%6,%7}, {%8,%9}, {%0,%1,%2,%3};"
        : "+f"(c[0]), "+f"(c[1]), "+f"(c[2]), "+f"(c[3])
        : "r"(a[0]), "r"(a[1]), "r"(a[2]), "r"(a[3]), "r"(b0), "r"(b1));
}
__device__ __forceinline__ void cp16(unsigned int dst, const void* src) {
    asm volatile("cp.async.cg.shared.global [%0], [%1], 16;"
                 :: "r"(dst), "l"(__cvta_generic_to_global(src)) : "memory");
}
#define CP_COMMIT() asm volatile("cp.async.commit_group;" ::: "memory")
#define CP_WAIT1()  asm volatile("cp.async.wait_group 1;" ::: "memory")

__device__ __forceinline__ unsigned int sw128(unsigned int b) {
    return b ^ ((b >> 3) & 0x70);
}
// [128 x 128] bf16 K-major tile = two 64-k planes of 16KB, 128B rows
__device__ __forceinline__ unsigned int tile_off(int row, int k) {
    return ((unsigned)(k >> 6) << 14) + ((unsigned)row << 7) + ((unsigned)(k & 63) << 1);
}
__device__ __forceinline__ unsigned int pack2bf(float a, float b) {
    __nv_bfloat162 p = __floats2bfloat162_rn(a, b);
    return *reinterpret_cast<unsigned int*>(&p);
}

// ---------------- Kernel 0: V -> bf16 hi/lo planes ----------------
__global__ void conv_kernel(const float4* __restrict__ X4, int n4) {
    int i = blockIdx.x * blockDim.x + threadIdx.x;
    if (i < n4) {
        float4 v = X4[i];
        float vv[4] = {v.x, v.y, v.z, v.w};
        float hf[4];
#pragma unroll
        for (int q = 0; q < 4; q++)
            hf[q] = __bfloat162float(__float2bfloat16(vv[q]));
        uint2 hi = make_uint2(pack2bf(hf[0], hf[1]), pack2bf(hf[2], hf[3]));
        uint2 lo = make_uint2(pack2bf(vv[0] - hf[0], vv[1] - hf[1]),
                              pack2bf(vv[2] - hf[2], vv[3] - hf[3]));
        reinterpret_cast<uint2*>(g_Vh)[i] = hi;
        reinterpret_cast<uint2*>(g_Vl)[i] = lo;
    }
}

// ---------------- Kernel 1: gather-aggregate from bf16 V ----------------
__global__ void agg_kernel(const int* __restrict__ nh_idx,
                           const int* __restrict__ int_idx,
                           const float* __restrict__ nh_e,
                           const float* __restrict__ int_e,
                           int n) {
    int node = blockIdx.x * (blockDim.x >> 5) + (threadIdx.x >> 5);
    if (node >= n) return;
    int lane = threadIdx.x & 31;
    const uint2* Vb2 = reinterpret_cast<const uint2*>(g_Vh);

    int   iA = -1, iB = -1;
    float eA = 0.f, eB = 0.f;
    if (lane < KNBR) {
        int base = node * KNBR + lane;
        iA = nh_idx[base];
        eA = nh_e[base];
        iB = int_idx[base];
        eB = int_e[base];
    }
    int validB = __popc(__ballot_sync(0xffffffffu, (lane < KNBR) && (iB >= 0)));

    float4 acc = make_float4(0.f, 0.f, 0.f, 0.f);
#pragma unroll
    for (int j = 0; j < KNBR; j++) {
        int   idx = __shfl_sync(0xffffffffu, iA, j);
        float e   = __shfl_sync(0xffffffffu, eA, j);
        uint2 u   = __ldg(&Vb2[idx * 32 + lane]);
        __nv_bfloat162 p0 = *reinterpret_cast<__nv_bfloat162*>(&u.x);
        __nv_bfloat162 p1 = *reinterpret_cast<__nv_bfloat162*>(&u.y);
        acc.x = fmaf(e, __bfloat162float(p0.x), acc.x);
        acc.y = fmaf(e, __bfloat162float(p0.y), acc.y);
        acc.z = fmaf(e, __bfloat162float(p1.x), acc.z);
        acc.w = fmaf(e, __bfloat162float(p1.y), acc.w);
    }
#pragma unroll
    for (int j = 0; j < KNBR; j++) {
        int idx = __shfl_sync(0xffffffffu, iB, j);
        if (idx >= 0) {
            float e  = __shfl_sync(0xffffffffu, eB, j);
            uint2 u  = __ldg(&Vb2[idx * 32 + lane]);
            __nv_bfloat162 p0 = *reinterpret_cast<__nv_bfloat162*>(&u.x);
            __nv_bfloat162 p1 = *reinterpret_cast<__nv_bfloat162*>(&u.y);
            acc.x = fmaf(e, __bfloat162float(p0.x), acc.x);
            acc.y = fmaf(e, __bfloat162float(p0.y), acc.y);
            acc.z = fmaf(e, __bfloat162float(p1.x), acc.z);
            acc.w = fmaf(e, __bfloat162float(p1.y), acc.w);
        }
    }
    float inv = 1.0f / (float)(KNBR + validB);
    float gv[4] = {acc.x * inv, acc.y * inv, acc.z * inv, acc.w * inv};
    float hf[4];
#pragma unroll
    for (int q = 0; q < 4; q++)
        hf[q] = __bfloat162float(__float2bfloat16(gv[q]));
    uint2 hi = make_uint2(pack2bf(hf[0], hf[1]), pack2bf(hf[2], hf[3]));
    uint2 lo = make_uint2(pack2bf(gv[0] - hf[0], gv[1] - hf[1]),
                          pack2bf(gv[2] - hf[2], gv[3] - hf[3]));
    reinterpret_cast<uint2*>(g_Gh)[node * 32 + lane] = hi;
    reinterpret_cast<uint2*>(g_Gl)[node * 32 + lane] = lo;
}

// =================== smem layout for gemm (dynamic) ===================
// [0]       weights: Wc_h, Wc_l, Wn_h, Wn_l (each 32KB, [n][k] K-major SW128)
// [131072]  A chunk double buffer: 2 x {hi 16KB, lo 16KB}
#define SM_B 0u
#define SM_A 131072u
#define SM_TOTAL 196608

// ---------------- Kernel 2: pipelined HMMA 3-term dual GEMM ----------------
__global__ __launch_bounds__(512, 1)
void gemm_tc(const float* __restrict__ Wvc,
             const float* __restrict__ Wvn,
             const float* __restrict__ bv,
             float* __restrict__ out,
             int n, int ntiles) {
    extern __shared__ char smem[];
    unsigned int sb = smem_u32(smem);
    const int tid = threadIdx.x;
    const int wid = tid >> 5;
    const int lane = tid & 31;

    // chunk loader: 32KB (hi+lo planes of one 64-k half) via cp.async
    auto load_chunk = [&](int buf, int tile, int s, int h) {
        const __nv_bfloat16* srcH = s ? g_Gh : g_Vh;
        const __nv_bfloat16* srcL = s ? g_Gl : g_Vl;
        unsigned int dstBase = sb + SM_A + (unsigned)buf * 32768u;
#pragma unroll
        for (int i = 0; i < 2; i++) {
            int idx = i * 512 + tid;       // 0..1023
            int row = idx >> 3;
            int u   = idx & 7;             // 16B unit within 128B row-half
            int gr = tile * 128 + row;
            if (gr >= n) gr = n - 1;
            unsigned int off = sw128((unsigned)(row * 128 + u * 16));
            long long sOff = (long long)gr * 256 + h * 128 + u * 16;
            cp16(dstBase + off, (const char*)srcH + sOff);
            cp16(dstBase + 16384u + off, (const char*)srcL + sOff);
        }
    };

    // ---- kick off first chunk load, then convert weights while it flies ----
    if (blockIdx.x < (unsigned)ntiles) load_chunk(0, blockIdx.x, 0, 0);
    CP_COMMIT();

    for (int m = 0; m < 2; m++) {
        const float* W = m ? Wvn : Wvc;
        char* bh = smem + SM_B + m * 65536;
        char* bl = bh + 32768;
        for (int idx = tid; idx < 4096; idx += 512) {
            int k  = idx >> 5;
            int n4 = (idx & 31) << 2;
            float4 w = *reinterpret_cast<const float4*>(W + k * FEATS + n4);
            float wv[4] = {w.x, w.y, w.z, w.w};
#pragma unroll
            for (int i = 0; i < 4; i++) {
                __nv_bfloat16 h = __float2bfloat16(wv[i]);
                float hf = __bfloat162float(h);
                __nv_bfloat16 l = __float2bfloat16(wv[i] - hf);
                unsigned int off = sw128(tile_off(n4 + i, k));
                *reinterpret_cast<__nv_bfloat16*>(bh + off) = h;
                *reinterpret_cast<__nv_bfloat16*>(bl + off) = l;
            }
        }
    }

    // ---- per-warp ldmatrix addresses (pure-XOR SW128 form, within-plane) ----
    const int wm = wid & 3;        // 32-row block
    const int wn = wid >> 2;       // 32-col block
    const int mIdx = lane >> 3;
    const int r8 = lane & 7;

    const int rowA = wm * 32 + ((mIdx & 1) << 3) + r8;
    const unsigned int prowA =
        ((unsigned)rowA << 7) ^ (((unsigned)rowA & 7) << 4) ^ (((unsigned)mIdx >> 1) << 4);
    const int rowB = wn * 32 + ((mIdx >> 1) << 3) + r8;
    const unsigned int prowB =
        ((unsigned)rowB << 7) ^ (((unsigned)rowB & 7) << 4) ^ (((unsigned)mIdx & 1) << 4);

    float2 biasj[4];
#pragma unroll
    for (int j = 0; j < 4; j++) {
        int c = wn * 32 + j * 8 + ((lane & 3) << 1);
        biasj[j].x = __ldg(bv + c);
        biasj[j].y = __ldg(bv + c + 1);
    }

    for (int tile = blockIdx.x; tile < ntiles; tile += gridDim.x) {
        float acc[2][4][4];
#pragma unroll
        for (int i = 0; i < 2; i++)
#pragma unroll
            for (int j = 0; j < 4; j++)
#pragma unroll
                for (int q = 0; q < 4; q++) acc[i][j][q] = 0.f;

        int buf = 0;
#pragma unroll
        for (int c = 0; c < 4; c++) {
            const int s = c >> 1, h = c & 1;
            __syncthreads();  // prior MMA readers of buf^1 are done
            if (c < 3) {
                load_chunk(buf ^ 1, tile, (c + 1) >> 1, (c + 1) & 1);
            } else {
                int nt = tile + gridDim.x;
                if (nt < ntiles) load_chunk(buf ^ 1, nt, 0, 0);
            }
            CP_COMMIT();
            CP_WAIT1();       // current chunk's data has landed (per-thread)
            __syncthreads();  // ... and is visible CTA-wide

            const unsigned int aHp = sb + SM_A + (unsigned)buf * 32768u;
            const unsigned int aLp = aHp + 16384u;
            const unsigned int bHp = sb + SM_B + (unsigned)s * 65536u + (unsigned)h * 16384u;
            const unsigned int bLp = bHp + 32768u;

#pragma unroll
            for (int ks = 0; ks < 4; ks++) {
                const unsigned int Kc = (unsigned)ks << 5;
                unsigned int ah[2][4], al[2][4], bh[2][4], bl[2][4];
                ldsm4(ah[0], aHp + (prowA ^ Kc));
                ldsm4(ah[1], aHp + (prowA ^ 0x800u ^ Kc));
                ldsm4(al[0], aLp + (prowA ^ Kc));
                ldsm4(al[1], aLp + (prowA ^ 0x800u ^ Kc));
                ldsm4(bh[0], bHp + (prowB ^ Kc));
                ldsm4(bh[1], bHp + (prowB ^ 0x800u ^ Kc));
                ldsm4(bl[0], bLp + (prowB ^ Kc));
                ldsm4(bl[1], bLp + (prowB ^ 0x800u ^ Kc));
#pragma unroll
                for (int i = 0; i < 2; i++) {
#pragma unroll
                    for (int j = 0; j < 4; j++) {
                        unsigned int b0h = bh[j >> 1][(j & 1) * 2];
                        unsigned int b1h = bh[j >> 1][(j & 1) * 2 + 1];
                        unsigned int b0l = bl[j >> 1][(j & 1) * 2];
                        unsigned int b1l = bl[j >> 1][(j & 1) * 2 + 1];
                        mma16816(acc[i][j], ah[i], b0h, b1h);  // Ah*Bh
                        mma16816(acc[i][j], ah[i], b0l, b1l);  // Ah*Bl
                        mma16816(acc[i][j], al[i], b0h, b1h);  // Al*Bh
                    }
                }
            }
            buf ^= 1;
        }

        // ---- epilogue (overlaps next tile's prefetch) ----
        int row_base = tile * 128 + wm * 32 + (lane >> 2);
#pragma unroll
        for (int i = 0; i < 2; i++) {
            int r0 = row_base + i * 16;
            int r1 = r0 + 8;
#pragma unroll
            for (int j = 0; j < 4; j++) {
                int col = wn * 32 + j * 8 + ((lane & 3) << 1);
                if (r0 < n) {
                    float2 o;
                    o.x = fmaxf(acc[i][j][0] + biasj[j].x, 0.f);
                    o.y = fmaxf(acc[i][j][1] + biasj[j].y, 0.f);
                    *reinterpret_cast<float2*>(out + (long long)r0 * FEATS + col) = o;
                }
                if (r1 < n) {
                    float2 o;
                    o.x = fmaxf(acc[i][j][2] + biasj[j].x, 0.f);
                    o.y = fmaxf(acc[i][j][3] + biasj[j].y, 0.f);
                    *reinterpret_cast<float2*>(out + (long long)r1 * FEATS + col) = o;
                }
            }
        }
    }
}

extern "C" void kernel_launch(void* const* d_in, const int* in_sizes, int n_in,
                              void* d_out, int out_size) {
    const float* vertices = (const float*)d_in[0];
    const int*   nh_idx   = (const int*)d_in[1];
    const int*   int_idx  = (const int*)d_in[2];
    const float* nh_e     = (const float*)d_in[3];
    const float* int_e    = (const float*)d_in[4];
    const float* Wvc      = (const float*)d_in[5];
    const float* Wvn      = (const float*)d_in[6];
    const float* bv       = (const float*)d_in[7];
    float* out = (float*)d_out;

    int n = in_sizes[0] / FEATS;  // 50000

    int n4 = n * 32;
    conv_kernel<<<(n4 + 255) / 256, 256>>>((const float4*)vertices, n4);

    agg_kernel<<<(n + 7) / 8, 256>>>(nh_idx, int_idx, nh_e, int_e, n);

    int ntiles = (n + 127) / 128;
    int grid = ntiles < 148 ? ntiles : 148;
    cudaFuncSetAttribute(gemm_tc, cudaFuncAttributeMaxDynamicSharedMemorySize, SM_TOTAL);
    gemm_tc<<<grid, 512, SM_TOTAL>>>(Wvc, Wvn, bv, out, n, ntiles);
}